// round 16
// baseline (speedup 1.0000x reference)
#include <cuda_runtime.h>
#include <cuda_bf16.h>
#include <cuda_fp16.h>

// ---------------------------------------------------------------------------
// TensorCircuit forward — ONE persistent kernel, software grid barriers.
// Linear domain, no renormalization:
//   input:  lin0[i,b] = softmax(in_logits[i])[x[b, i/32]]          (bf16)
//   prod1:  em1[e,b]  = lin0[p0,b]*lin0[p1,b] * 2^14               (fp8 e5m2)
//   sum1:   s1[s,b]   = 2^-14 * sum_c w~[s,c]*em1[cid,b]           (bf16, f16x2 acc)
//   prod2/3, sum2/3: bf16 gathers, fp32 accumulation (values in (0,1];
//   worst-case em3 ~1e-32 is inside bf16 range).
//   root: acc = sum_c w4_c * (s3[p0]*2^60)*(s3[p1]*2^60); out = log(acc)-120ln2.
//
// Grid = 148*4 = 592 blocks x 256 threads, __launch_bounds__(256,4) ->
// all blocks resident -> software barrier is deadlock-free.
// Barrier counters are MONOTONIC (never reset) -> safe across graph replays.
// ---------------------------------------------------------------------------

#define BATCH 1024
#define NV    256
#define NK    64
#define NM    32
#define GRID  592u

// bf16 arena (element offsets).
#define LIN0  0u
#define EMO   (8192u * 1024u)
#define S1O   (EMO + 8192u * 1024u)
#define S2O   (S1O + 4096u * 1024u)
#define S3O   (S2O + 2048u * 1024u)
#define BF_SZ (S3O + 1024u * 1024u)

__device__ __nv_bfloat16 g_bf[BF_SZ];
__device__ unsigned char g_e8[8192u * 1024u];   // em1, fp8 e5m2 (scaled 2^14)
__device__ unsigned     g_bar[8];               // monotonic barrier counters

#define EM1_SCALE    16384.0f
#define EM1_INVSCALE (1.0f / 16384.0f)
#define S3_SCALE     1.152921504606847e18f      // 2^60
#define LOG_S3SQ     83.17766166719344f         // 120 * ln(2)

// --- packing helpers ---------------------------------------------------------
__device__ __forceinline__ float lo_bf(unsigned u) { return __uint_as_float(u << 16); }
__device__ __forceinline__ float hi_bf(unsigned u) { return __uint_as_float(u & 0xffff0000u); }
__device__ __forceinline__ unsigned pack_bf2(float lo, float hi) {
    unsigned r;
    asm("cvt.rn.bf16x2.f32 %0, %1, %2;" : "=r"(r) : "f"(hi), "f"(lo));
    return r;
}
__device__ __forceinline__ unsigned short pack_e5(float lo, float hi) {
    unsigned short r;
    asm("cvt.rn.satfinite.e5m2x2.f32 %0, %1, %2;" : "=h"(r) : "f"(hi), "f"(lo));
    return r;
}
__device__ __forceinline__ __half2 unpack_e5(unsigned short v) {
    unsigned r;
    asm("cvt.rn.f16x2.e5m2x2 %0, %1;" : "=r"(r) : "h"(v));
    return *(__half2*)&r;
}

// Software grid barrier, replay-safe (monotonic counters, never reset).
// All blocks of one launch get 'old' in [r*G, (r+1)*G) -> common target.
__device__ __forceinline__ void gridbar(int k) {
    __syncthreads();
    if (threadIdx.x == 0) {
        __threadfence();                       // release this block's stores
        unsigned old = atomicAdd(&g_bar[k], 1u);
        unsigned target = (old / GRID + 1u) * GRID;
        while (*(volatile unsigned*)&g_bar[k] < target) __nanosleep(64);
        __threadfence();                       // acquire others' stores
    }
    __syncthreads();
}

// Per-half sum-node weight prep: softmax over 32 weights (one warp), result
// + child byte offset packed into smem. 'scale_half' selects half2 packing
// (for the fp8 layer) vs fp32 bits.
__device__ __forceinline__ void prep_w(uint2* swc, const int* cids,
                                       const float* w, int node, int lane,
                                       unsigned row_bytes, bool as_half2) {
    float wv = w[node * 32 + lane];
    float mx = wv;
#pragma unroll
    for (int o = 16; o; o >>= 1) mx = fmaxf(mx, __shfl_xor_sync(0xffffffffu, mx, o));
    float e = __expf(wv - mx);
    float sm = e;
#pragma unroll
    for (int o = 16; o; o >>= 1) sm += __shfl_xor_sync(0xffffffffu, sm, o);
    float wn = e * __frcp_rn(sm);
    unsigned wb;
    if (as_half2) { __half2 wh = __float2half2_rn(wn); wb = *(unsigned*)&wh; }
    else          { wb = __float_as_uint(wn); }
    swc[lane] = make_uint2(wb, (unsigned)(cids[node * 32 + lane] - 1) * row_bytes);
}

__global__ void __launch_bounds__(256, 4) k_all(
    float* __restrict__ out,
    const int* __restrict__ x, const float* __restrict__ logits,
    const float* __restrict__ w1, const float* __restrict__ w2,
    const float* __restrict__ w3, const float* __restrict__ w4,
    const int* __restrict__ pids1, const int* __restrict__ pids2,
    const int* __restrict__ pids3, const int* __restrict__ pids4,
    const int* __restrict__ cids1, const int* __restrict__ cids2,
    const int* __restrict__ cids3, const int* __restrict__ cids4)
{
    __shared__ float Pt[NK][NM + 1];     // input softmax tile
    __shared__ uint2 swc[2][32];         // per-half sum weights+offsets
    const int tid  = threadIdx.x;
    const int half = tid >> 7, ht = tid & 127;
    const int warp = tid >> 5, lane = tid & 31;

    // ---- Phase 0: input layer (softmax tile + gather), 256 variables ------
    for (unsigned v = blockIdx.x; v < NV; v += GRID) {
#pragma unroll
        for (int i = 0; i < 4; i++) {
            int m = warp * 4 + i;
            const float* lr = logits + (v * NM + m) * NK;
            float v0 = lr[lane], v1 = lr[lane + 32];
            float mx = fmaxf(v0, v1);
#pragma unroll
            for (int o = 16; o; o >>= 1) mx = fmaxf(mx, __shfl_xor_sync(0xffffffffu, mx, o));
            float e0 = __expf(v0 - mx), e1 = __expf(v1 - mx);
            float sm = e0 + e1;
#pragma unroll
            for (int o = 16; o; o >>= 1) sm += __shfl_xor_sync(0xffffffffu, sm, o);
            float inv = __frcp_rn(sm);
            Pt[lane][m]      = e0 * inv;
            Pt[lane + 32][m] = e1 * inv;
        }
        __syncthreads();
#pragma unroll
        for (int j = 0; j < 2; j++) {
            int b = (tid + j * 256) * 2;
            int i0 = x[b * NV + v];
            int i1 = x[(b + 1) * NV + v];
            unsigned* o = (unsigned*)((unsigned short*)(g_bf + LIN0)
                                      + (unsigned)(v * NM) * BATCH + b);
#pragma unroll
            for (int m = 0; m < NM; m++)
                o[m * (BATCH / 2)] = pack_bf2(Pt[i0][m], Pt[i1][m]);
        }
        __syncthreads();                 // Pt reused next iteration
    }
    gridbar(0);

    // ---- Phase 1: prod1 -> fp8 em1 (2048 items x 4 elements) --------------
    for (unsigned it = blockIdx.x; it < 2048; it += GRID) {
        unsigned e0 = it * 4 + half;
        const int* pp = pids1 + e0 * 2;
        int p00 = __ldg(pp) - 1,     p01 = __ldg(pp + 1) - 1;
        int p10 = __ldg(pp + 4) - 1, p11 = __ldg(pp + 5) - 1;
        const uint4* prev = (const uint4*)(g_bf + LIN0);
        uint4 ua0 = prev[(unsigned)p00 * 128 + ht];
        uint4 ub0 = prev[(unsigned)p01 * 128 + ht];
        uint4 ua1 = prev[(unsigned)p10 * 128 + ht];
        uint4 ub1 = prev[(unsigned)p11 * 128 + ht];
        float r0[8], r1[8];
        r0[0] = lo_bf(ua0.x) * lo_bf(ub0.x);  r0[1] = hi_bf(ua0.x) * hi_bf(ub0.x);
        r0[2] = lo_bf(ua0.y) * lo_bf(ub0.y);  r0[3] = hi_bf(ua0.y) * hi_bf(ub0.y);
        r0[4] = lo_bf(ua0.z) * lo_bf(ub0.z);  r0[5] = hi_bf(ua0.z) * hi_bf(ub0.z);
        r0[6] = lo_bf(ua0.w) * lo_bf(ub0.w);  r0[7] = hi_bf(ua0.w) * hi_bf(ub0.w);
        r1[0] = lo_bf(ua1.x) * lo_bf(ub1.x);  r1[1] = hi_bf(ua1.x) * hi_bf(ub1.x);
        r1[2] = lo_bf(ua1.y) * lo_bf(ub1.y);  r1[3] = hi_bf(ua1.y) * hi_bf(ub1.y);
        r1[4] = lo_bf(ua1.z) * lo_bf(ub1.z);  r1[5] = hi_bf(ua1.z) * hi_bf(ub1.z);
        r1[6] = lo_bf(ua1.w) * lo_bf(ub1.w);  r1[7] = hi_bf(ua1.w) * hi_bf(ub1.w);
#pragma unroll
        for (int j = 0; j < 8; j++) { r0[j] *= EM1_SCALE; r1[j] *= EM1_SCALE; }
        uint2 o0, o1;
        o0.x = (unsigned)pack_e5(r0[0], r0[1]) | ((unsigned)pack_e5(r0[2], r0[3]) << 16);
        o0.y = (unsigned)pack_e5(r0[4], r0[5]) | ((unsigned)pack_e5(r0[6], r0[7]) << 16);
        o1.x = (unsigned)pack_e5(r1[0], r1[1]) | ((unsigned)pack_e5(r1[2], r1[3]) << 16);
        o1.y = (unsigned)pack_e5(r1[4], r1[5]) | ((unsigned)pack_e5(r1[6], r1[7]) << 16);
        uint2* o = (uint2*)g_e8;
        o[e0 * 128 + ht]       = o0;
        o[(e0 + 2) * 128 + ht] = o1;
    }
    gridbar(1);

    // ---- Phase 2: sum1 over fp8 (2048 items x 2 nodes, f16x2 acc) ---------
    for (unsigned it = blockIdx.x; it < 2048; it += GRID) {
        int node = it * 2 + half;
        if (ht < 32) prep_w(swc[half], cids1, w1, node, ht, 1024u, true);
        __syncthreads();
        const char* base = (const char*)g_e8 + ht * 8;
        __half2 acc0 = __float2half2_rn(0.f), acc1 = acc0, acc2 = acc0, acc3 = acc0;
#pragma unroll
        for (int c = 0; c < 32; c++) {
            uint2 wc = swc[half][c];
            uint2 u = *(const uint2*)(base + wc.y);
            __half2 wh = *(__half2*)&wc.x;
            acc0 = __hfma2(wh, unpack_e5((unsigned short)(u.x & 0xffffu)), acc0);
            acc1 = __hfma2(wh, unpack_e5((unsigned short)(u.x >> 16)),     acc1);
            acc2 = __hfma2(wh, unpack_e5((unsigned short)(u.y & 0xffffu)), acc2);
            acc3 = __hfma2(wh, unpack_e5((unsigned short)(u.y >> 16)),     acc3);
        }
        float2 v0 = __half22float2(acc0), v1 = __half22float2(acc1);
        float2 v2 = __half22float2(acc2), v3 = __half22float2(acc3);
        uint4 o;
        o.x = pack_bf2(v0.x * EM1_INVSCALE, v0.y * EM1_INVSCALE);
        o.y = pack_bf2(v1.x * EM1_INVSCALE, v1.y * EM1_INVSCALE);
        o.z = pack_bf2(v2.x * EM1_INVSCALE, v2.y * EM1_INVSCALE);
        o.w = pack_bf2(v3.x * EM1_INVSCALE, v3.y * EM1_INVSCALE);
        ((uint4*)(g_bf + S1O))[node * 128 + ht] = o;
        __syncthreads();                 // swc reused next iteration
    }
    gridbar(2);

    // ---- Phases 3..6: bf16 prod/sum for layers 2 and 3 --------------------
#pragma unroll 1
    for (int layer = 0; layer < 2; layer++) {
        unsigned prev_off = layer ? S2O : S1O;
        unsigned sout_off = layer ? S3O : S2O;
        const int* pids = layer ? pids3 : pids2;
        const int* cids = layer ? cids3 : cids2;
        const float* w  = layer ? w3 : w2;
        int start       = layer ? (1 + 8192 + 4096) : (1 + 8192);
        unsigned n_prod = layer ? 512u : 1024u;    // E/4
        unsigned n_sum  = layer ? 512u : 1024u;    // S/2

        for (unsigned it = blockIdx.x; it < n_prod; it += GRID) {
            unsigned e0 = it * 4 + half;
            const int* pp = pids + e0 * 2;
            int p00 = __ldg(pp) - start,     p01 = __ldg(pp + 1) - start;
            int p10 = __ldg(pp + 4) - start, p11 = __ldg(pp + 5) - start;
            const uint4* prev = (const uint4*)(g_bf + prev_off);
            uint4 ua0 = prev[(unsigned)p00 * 128 + ht];
            uint4 ub0 = prev[(unsigned)p01 * 128 + ht];
            uint4 ua1 = prev[(unsigned)p10 * 128 + ht];
            uint4 ub1 = prev[(unsigned)p11 * 128 + ht];
            uint4 o0, o1;
            o0.x = pack_bf2(lo_bf(ua0.x) * lo_bf(ub0.x), hi_bf(ua0.x) * hi_bf(ub0.x));
            o0.y = pack_bf2(lo_bf(ua0.y) * lo_bf(ub0.y), hi_bf(ua0.y) * hi_bf(ub0.y));
            o0.z = pack_bf2(lo_bf(ua0.z) * lo_bf(ub0.z), hi_bf(ua0.z) * hi_bf(ub0.z));
            o0.w = pack_bf2(lo_bf(ua0.w) * lo_bf(ub0.w), hi_bf(ua0.w) * hi_bf(ub0.w));
            o1.x = pack_bf2(lo_bf(ua1.x) * lo_bf(ub1.x), hi_bf(ua1.x) * hi_bf(ub1.x));
            o1.y = pack_bf2(lo_bf(ua1.y) * lo_bf(ub1.y), hi_bf(ua1.y) * hi_bf(ub1.y));
            o1.z = pack_bf2(lo_bf(ua1.z) * lo_bf(ub1.z), hi_bf(ua1.z) * hi_bf(ub1.z));
            o1.w = pack_bf2(lo_bf(ua1.w) * lo_bf(ub1.w), hi_bf(ua1.w) * hi_bf(ub1.w));
            uint4* o = (uint4*)(g_bf + EMO);
            o[e0 * 128 + ht]       = o0;
            o[(e0 + 2) * 128 + ht] = o1;
        }
        gridbar(3 + layer * 2);

        for (unsigned it = blockIdx.x; it < n_sum; it += GRID) {
            int node = it * 2 + half;
            if (ht < 32) prep_w(swc[half], cids, w, node, ht, 2048u, false);
            __syncthreads();
            const char* base = (const char*)(g_bf + EMO) + ht * 16;
            float a0 = 0.f, a1 = 0.f, a2 = 0.f, a3 = 0.f;
            float a4 = 0.f, a5 = 0.f, a6 = 0.f, a7 = 0.f;
#pragma unroll
            for (int c = 0; c < 32; c++) {
                uint2 wc = swc[half][c];
                uint4 u = *(const uint4*)(base + wc.y);
                float wv = __uint_as_float(wc.x);
                a0 = fmaf(wv, lo_bf(u.x), a0);  a1 = fmaf(wv, hi_bf(u.x), a1);
                a2 = fmaf(wv, lo_bf(u.y), a2);  a3 = fmaf(wv, hi_bf(u.y), a3);
                a4 = fmaf(wv, lo_bf(u.z), a4);  a5 = fmaf(wv, hi_bf(u.z), a5);
                a6 = fmaf(wv, lo_bf(u.w), a6);  a7 = fmaf(wv, hi_bf(u.w), a7);
            }
            uint4 o;
            o.x = pack_bf2(a0, a1);  o.y = pack_bf2(a2, a3);
            o.z = pack_bf2(a4, a5);  o.w = pack_bf2(a6, a7);
            ((uint4*)(g_bf + sout_off))[node * 128 + ht] = o;
            __syncthreads();             // swc reused next iteration
        }
        gridbar(4 + layer * 2);
    }

    // ---- Phase 7: root (block 0 only) --------------------------------------
    if (blockIdx.x == 0) {
        __shared__ float sw[32];
        __shared__ int   sp0[32], sp1[32];
        if (tid < 32) {
            float wv = w4[tid];
            float mx = wv;
#pragma unroll
            for (int o = 16; o; o >>= 1) mx = fmaxf(mx, __shfl_xor_sync(0xffffffffu, mx, o));
            float e = __expf(wv - mx);
            float sm = e;
#pragma unroll
            for (int o = 16; o; o >>= 1) sm += __shfl_xor_sync(0xffffffffu, sm, o);
            sw[tid] = e * __frcp_rn(sm);
            int elem = cids4[tid] - 1;
            const int start4 = 1 + 8192 + 4096 + 2048;
            sp0[tid] = __ldg(&pids4[elem * 2])     - start4;
            sp1[tid] = __ldg(&pids4[elem * 2 + 1]) - start4;
        }
        __syncthreads();
        const uint2* s3 = (const uint2*)(g_bf + S3O);
        float a0 = 0.f, a1 = 0.f, a2 = 0.f, a3 = 0.f;
#pragma unroll
        for (int c = 0; c < 32; c++) {
            uint2 u0 = s3[(unsigned)sp0[c] * 256 + tid];
            uint2 u1 = s3[(unsigned)sp1[c] * 256 + tid];
            float wv = sw[c];
            a0 = fmaf(wv, (lo_bf(u0.x) * S3_SCALE) * (lo_bf(u1.x) * S3_SCALE), a0);
            a1 = fmaf(wv, (hi_bf(u0.x) * S3_SCALE) * (hi_bf(u1.x) * S3_SCALE), a1);
            a2 = fmaf(wv, (lo_bf(u0.y) * S3_SCALE) * (lo_bf(u1.y) * S3_SCALE), a2);
            a3 = fmaf(wv, (hi_bf(u0.y) * S3_SCALE) * (hi_bf(u1.y) * S3_SCALE), a3);
        }
        float4 o;
        o.x = logf(a0) - LOG_S3SQ;
        o.y = logf(a1) - LOG_S3SQ;
        o.z = logf(a2) - LOG_S3SQ;
        o.w = logf(a3) - LOG_S3SQ;
        ((float4*)out)[tid] = o;
    }
}

extern "C" void kernel_launch(void* const* d_in, const int* in_sizes, int n_in,
                              void* d_out, int out_size) {
    const int*   x      = (const int*)d_in[0];
    const float* logits = (const float*)d_in[1];
    const float* w1     = (const float*)d_in[2];
    const float* w2     = (const float*)d_in[3];
    const float* w3     = (const float*)d_in[4];
    const float* w4     = (const float*)d_in[5];
    const int*   pids1  = (const int*)d_in[6];
    const int*   pids2  = (const int*)d_in[7];
    const int*   pids3  = (const int*)d_in[8];
    const int*   pids4  = (const int*)d_in[9];
    const int*   cids1  = (const int*)d_in[10];
    const int*   cids2  = (const int*)d_in[11];
    const int*   cids3  = (const int*)d_in[12];
    const int*   cids4  = (const int*)d_in[13];

    k_all<<<GRID, 256>>>((float*)d_out, x, logits, w1, w2, w3, w4,
                         pids1, pids2, pids3, pids4,
                         cids1, cids2, cids3, cids4);
}

// round 17
// speedup vs baseline: 1.2098x; 1.2098x over previous
#include <cuda_runtime.h>
#include <cuda_bf16.h>
#include <cuda_fp16.h>

// ---------------------------------------------------------------------------
// TensorCircuit forward, linear domain, no renormalization. 8 kernels chained
// with PDL (programmatic dependent launch): each kernel does its independent
// prologue (pids / weight softmax from harness inputs), THEN
// cudaGridDependencySynchronize(), then the gathers that depend on the
// predecessor. Launch gaps overlap predecessor tails.
//   input:  lin0[i,b] = softmax(in_logits[i])[x[b, i/32]]          (bf16)
//   prod1:  em1[e,b]  = lin0[p0,b]*lin0[p1,b] * 2^14               (fp8 e5m2)
//   sum1:   s1[s,b]   = 2^-14 * sum_c w~[s,c]*em1[cid,b]           (bf16, f16x2 acc)
//   prod2/3, sum2/3: bf16 gathers, fp32 accumulation.
//   root: acc = sum_c w4_c * (s3[p0]*2^60)*(s3[p1]*2^60); out = log(acc)-120ln2.
// ---------------------------------------------------------------------------

#define BATCH 1024
#define NV    256
#define NK    64
#define NM    32

// bf16 arena (element offsets).
#define LIN0  0u
#define EMO   (8192u * 1024u)
#define S1O   (EMO + 8192u * 1024u)
#define S2O   (S1O + 4096u * 1024u)
#define S3O   (S2O + 2048u * 1024u)
#define BF_SZ (S3O + 1024u * 1024u)

__device__ __nv_bfloat16 g_bf[BF_SZ];
__device__ unsigned char g_e8[8192u * 1024u];   // em1, fp8 e5m2 (scaled 2^14)

#define EM1_SCALE    16384.0f
#define EM1_INVSCALE (1.0f / 16384.0f)
#define S3_SCALE     1.152921504606847e18f      // 2^60
#define LOG_S3SQ     83.17766166719344f         // 120 * ln(2)

// --- packing helpers ---------------------------------------------------------
__device__ __forceinline__ float lo_bf(unsigned u) { return __uint_as_float(u << 16); }
__device__ __forceinline__ float hi_bf(unsigned u) { return __uint_as_float(u & 0xffff0000u); }
__device__ __forceinline__ unsigned pack_bf2(float lo, float hi) {
    unsigned r;
    asm("cvt.rn.bf16x2.f32 %0, %1, %2;" : "=r"(r) : "f"(hi), "f"(lo));
    return r;
}
__device__ __forceinline__ unsigned short pack_e5(float lo, float hi) {
    unsigned short r;
    asm("cvt.rn.satfinite.e5m2x2.f32 %0, %1, %2;" : "=h"(r) : "f"(hi), "f"(lo));
    return r;
}
__device__ __forceinline__ __half2 unpack_e5(unsigned short v) {
    unsigned r;
    asm("cvt.rn.f16x2.e5m2x2 %0, %1;" : "=r"(r) : "h"(v));
    return *(__half2*)&r;
}

// Fused input layer: per-variable block computes the 32-row softmax tile in
// smem (transposed, padded), then each thread gathers for a COLUMN PAIR and
// writes packed bf16x2. Reads only harness inputs -> no dependency sync.
__global__ void __launch_bounds__(256) k_inp(const float* __restrict__ L,
                                             const int* __restrict__ x) {
    __shared__ float Pt[NK][NM + 1];
    int v = blockIdx.x;
    int warp = threadIdx.x >> 5, lane = threadIdx.x & 31;
#pragma unroll
    for (int i = 0; i < 4; i++) {
        int m = warp * 4 + i;
        const float* lr = L + (v * NM + m) * NK;
        float v0 = lr[lane], v1 = lr[lane + 32];
        float mx = fmaxf(v0, v1);
#pragma unroll
        for (int o = 16; o; o >>= 1) mx = fmaxf(mx, __shfl_xor_sync(0xffffffffu, mx, o));
        float e0 = __expf(v0 - mx), e1 = __expf(v1 - mx);
        float sm = e0 + e1;
#pragma unroll
        for (int o = 16; o; o >>= 1) sm += __shfl_xor_sync(0xffffffffu, sm, o);
        float inv = __frcp_rn(sm);
        Pt[lane][m]      = e0 * inv;
        Pt[lane + 32][m] = e1 * inv;
    }
    __syncthreads();
#pragma unroll
    for (int j = 0; j < 2; j++) {
        int b = (threadIdx.x + j * 256) * 2;
        int i0 = x[b * NV + v];
        int i1 = x[(b + 1) * NV + v];
        unsigned* o = (unsigned*)((unsigned short*)(g_bf + LIN0)
                                  + (unsigned)(v * NM) * BATCH + b);
#pragma unroll
        for (int m = 0; m < NM; m++)
            o[m * (BATCH / 2)] = pack_bf2(Pt[i0][m], Pt[i1][m]);
    }
}

// Layer-1 prod: em1[e,b] = lin0[p0,b]*lin0[p1,b] * 2^14, stored fp8 e5m2.
// pids prologue (independent) -> grid dep sync -> lin0 gathers.
__global__ void __launch_bounds__(256) k_prod8(const int* __restrict__ pids) {
    int tid = threadIdx.x;
    int half = tid >> 7, t = tid & 127;
    unsigned e0 = blockIdx.x * 4 + half;          // elements e0, e0+2
    const int* pp = pids + e0 * 2;
    int p00 = __ldg(pp)     - 1;
    int p01 = __ldg(pp + 1) - 1;
    int p10 = __ldg(pp + 4) - 1;
    int p11 = __ldg(pp + 5) - 1;
    cudaGridDependencySynchronize();              // wait for k_inp's lin0
    const uint4* prev = (const uint4*)(g_bf + LIN0);
    uint4 ua0 = prev[(unsigned)p00 * 128 + t];
    uint4 ub0 = prev[(unsigned)p01 * 128 + t];
    uint4 ua1 = prev[(unsigned)p10 * 128 + t];
    uint4 ub1 = prev[(unsigned)p11 * 128 + t];
    float r0[8], r1[8];
    r0[0] = lo_bf(ua0.x) * lo_bf(ub0.x);  r0[1] = hi_bf(ua0.x) * hi_bf(ub0.x);
    r0[2] = lo_bf(ua0.y) * lo_bf(ub0.y);  r0[3] = hi_bf(ua0.y) * hi_bf(ub0.y);
    r0[4] = lo_bf(ua0.z) * lo_bf(ub0.z);  r0[5] = hi_bf(ua0.z) * hi_bf(ub0.z);
    r0[6] = lo_bf(ua0.w) * lo_bf(ub0.w);  r0[7] = hi_bf(ua0.w) * hi_bf(ub0.w);
    r1[0] = lo_bf(ua1.x) * lo_bf(ub1.x);  r1[1] = hi_bf(ua1.x) * hi_bf(ub1.x);
    r1[2] = lo_bf(ua1.y) * lo_bf(ub1.y);  r1[3] = hi_bf(ua1.y) * hi_bf(ub1.y);
    r1[4] = lo_bf(ua1.z) * lo_bf(ub1.z);  r1[5] = hi_bf(ua1.z) * hi_bf(ub1.z);
    r1[6] = lo_bf(ua1.w) * lo_bf(ub1.w);  r1[7] = hi_bf(ua1.w) * hi_bf(ub1.w);
#pragma unroll
    for (int j = 0; j < 8; j++) { r0[j] *= EM1_SCALE; r1[j] *= EM1_SCALE; }
    uint2 o0, o1;
    o0.x = (unsigned)pack_e5(r0[0], r0[1]) | ((unsigned)pack_e5(r0[2], r0[3]) << 16);
    o0.y = (unsigned)pack_e5(r0[4], r0[5]) | ((unsigned)pack_e5(r0[6], r0[7]) << 16);
    o1.x = (unsigned)pack_e5(r1[0], r1[1]) | ((unsigned)pack_e5(r1[2], r1[3]) << 16);
    o1.y = (unsigned)pack_e5(r1[4], r1[5]) | ((unsigned)pack_e5(r1[6], r1[7]) << 16);
    uint2* out = (uint2*)g_e8;
    out[e0 * 128 + t]       = o0;
    out[(e0 + 2) * 128 + t] = o1;
}

// Layer-1 sum over fp8 em1. Weight softmax + cid prologue (independent) ->
// grid dep sync -> em1 gathers. f16x2 accumulation.
__global__ void __launch_bounds__(128) k_sum8(const int* __restrict__ cids,
                                              const float* __restrict__ w) {
    __shared__ uint2 swc[32];     // .x = half2(w,w) bits, .y = row byte offset
    int s = blockIdx.x, t = threadIdx.x;
    if (t < 32) {
        float wv = w[s * 32 + t];
        float mx = wv;
#pragma unroll
        for (int o = 16; o; o >>= 1) mx = fmaxf(mx, __shfl_xor_sync(0xffffffffu, mx, o));
        float e = __expf(wv - mx);
        float sm = e;
#pragma unroll
        for (int o = 16; o; o >>= 1) sm += __shfl_xor_sync(0xffffffffu, sm, o);
        __half2 wh = __float2half2_rn(e * __frcp_rn(sm));
        swc[t] = make_uint2(*(unsigned*)&wh, (unsigned)(cids[s * 32 + t] - 1) * 1024u);
    }
    __syncthreads();
    cudaGridDependencySynchronize();              // wait for k_prod8's em1
    const char* base = (const char*)g_e8 + t * 8;
    __half2 acc0 = __float2half2_rn(0.f), acc1 = acc0, acc2 = acc0, acc3 = acc0;
#pragma unroll
    for (int c = 0; c < 32; c++) {
        uint2 wc = swc[c];
        uint2 u = *(const uint2*)(base + wc.y);
        __half2 wh = *(__half2*)&wc.x;
        acc0 = __hfma2(wh, unpack_e5((unsigned short)(u.x & 0xffffu)), acc0);
        acc1 = __hfma2(wh, unpack_e5((unsigned short)(u.x >> 16)),     acc1);
        acc2 = __hfma2(wh, unpack_e5((unsigned short)(u.y & 0xffffu)), acc2);
        acc3 = __hfma2(wh, unpack_e5((unsigned short)(u.y >> 16)),     acc3);
    }
    float2 v0 = __half22float2(acc0), v1 = __half22float2(acc1);
    float2 v2 = __half22float2(acc2), v3 = __half22float2(acc3);
    uint4 o;
    o.x = pack_bf2(v0.x * EM1_INVSCALE, v0.y * EM1_INVSCALE);
    o.y = pack_bf2(v1.x * EM1_INVSCALE, v1.y * EM1_INVSCALE);
    o.z = pack_bf2(v2.x * EM1_INVSCALE, v2.y * EM1_INVSCALE);
    o.w = pack_bf2(v3.x * EM1_INVSCALE, v3.y * EM1_INVSCALE);
    ((uint4*)(g_bf + S1O))[s * 128 + t] = o;
}

// bf16 prod layer (layers 2-3). pids prologue -> grid dep sync -> gathers.
// NOTE: all g_bf writes are after the sync (prod3 overwrites EMO that sum2,
// its PDL primary, was reading).
__global__ void __launch_bounds__(256) k_prod(unsigned em_off, unsigned prev_off,
                                              const int* __restrict__ pids, int start) {
    int tid = threadIdx.x;
    int half = tid >> 7, t = tid & 127;
    unsigned e0 = blockIdx.x * 4 + half;
    const int* pp = pids + e0 * 2;
    int p00 = __ldg(pp)     - start;
    int p01 = __ldg(pp + 1) - start;
    int p10 = __ldg(pp + 4) - start;
    int p11 = __ldg(pp + 5) - start;
    cudaGridDependencySynchronize();              // wait for predecessor sum
    const uint4* prev = (const uint4*)(g_bf + prev_off);
    uint4 ua0 = prev[(unsigned)p00 * 128 + t];
    uint4 ub0 = prev[(unsigned)p01 * 128 + t];
    uint4 ua1 = prev[(unsigned)p10 * 128 + t];
    uint4 ub1 = prev[(unsigned)p11 * 128 + t];
    uint4 o0, o1;
    o0.x = pack_bf2(lo_bf(ua0.x) * lo_bf(ub0.x), hi_bf(ua0.x) * hi_bf(ub0.x));
    o0.y = pack_bf2(lo_bf(ua0.y) * lo_bf(ub0.y), hi_bf(ua0.y) * hi_bf(ub0.y));
    o0.z = pack_bf2(lo_bf(ua0.z) * lo_bf(ub0.z), hi_bf(ua0.z) * hi_bf(ub0.z));
    o0.w = pack_bf2(lo_bf(ua0.w) * lo_bf(ub0.w), hi_bf(ua0.w) * hi_bf(ub0.w));
    o1.x = pack_bf2(lo_bf(ua1.x) * lo_bf(ub1.x), hi_bf(ua1.x) * hi_bf(ub1.x));
    o1.y = pack_bf2(lo_bf(ua1.y) * lo_bf(ub1.y), hi_bf(ua1.y) * hi_bf(ub1.y));
    o1.z = pack_bf2(lo_bf(ua1.z) * lo_bf(ub1.z), hi_bf(ua1.z) * hi_bf(ub1.z));
    o1.w = pack_bf2(lo_bf(ua1.w) * lo_bf(ub1.w), hi_bf(ua1.w) * hi_bf(ub1.w));
    uint4* out = (uint4*)(g_bf + em_off);
    out[e0 * 128 + t]       = o0;
    out[(e0 + 2) * 128 + t] = o1;
}

// bf16 sum layer (layers 2-3). Weight prologue -> grid dep sync -> gathers.
__global__ void __launch_bounds__(128) k_sum(unsigned out_off, unsigned em_off,
                                             const int* __restrict__ cids,
                                             const float* __restrict__ w) {
    __shared__ uint2 swc[32];
    int s = blockIdx.x, t = threadIdx.x;
    if (t < 32) {
        float wv = w[s * 32 + t];
        float mx = wv;
#pragma unroll
        for (int o = 16; o; o >>= 1) mx = fmaxf(mx, __shfl_xor_sync(0xffffffffu, mx, o));
        float e = __expf(wv - mx);
        float sm = e;
#pragma unroll
        for (int o = 16; o; o >>= 1) sm += __shfl_xor_sync(0xffffffffu, sm, o);
        unsigned off = (unsigned)(cids[s * 32 + t] - 1) * 2048u;
        swc[t] = make_uint2(__float_as_uint(e * __frcp_rn(sm)), off);
    }
    __syncthreads();
    cudaGridDependencySynchronize();              // wait for predecessor prod
    const char* base = (const char*)(g_bf + em_off) + t * 16;
    float a0 = 0.f, a1 = 0.f, a2 = 0.f, a3 = 0.f;
    float a4 = 0.f, a5 = 0.f, a6 = 0.f, a7 = 0.f;
#pragma unroll
    for (int c = 0; c < 32; c++) {
        uint2 wc = swc[c];
        uint4 u = *(const uint4*)(base + wc.y);
        float wv = __uint_as_float(wc.x);
        a0 = fmaf(wv, lo_bf(u.x), a0);  a1 = fmaf(wv, hi_bf(u.x), a1);
        a2 = fmaf(wv, lo_bf(u.y), a2);  a3 = fmaf(wv, hi_bf(u.y), a3);
        a4 = fmaf(wv, lo_bf(u.z), a4);  a5 = fmaf(wv, hi_bf(u.z), a5);
        a6 = fmaf(wv, lo_bf(u.w), a6);  a7 = fmaf(wv, hi_bf(u.w), a7);
    }
    uint4 o;
    o.x = pack_bf2(a0, a1);  o.y = pack_bf2(a2, a3);
    o.z = pack_bf2(a4, a5);  o.w = pack_bf2(a6, a7);
    ((uint4*)(g_bf + out_off))[s * 128 + t] = o;
}

// Root: fused layer-4 prod + root sum over the 32 referenced elements.
// s3 scaled by 2^60 at load; out = log(acc) - 120*ln2.
__global__ void __launch_bounds__(256) k_root(float* __restrict__ out,
                                              const int* __restrict__ cids,
                                              const int* __restrict__ pids,
                                              const float* __restrict__ w) {
    __shared__ float sw[32];
    __shared__ int   sp0[32], sp1[32];
    int t = threadIdx.x;
    if (t < 32) {
        float wv = w[t];
        float mx = wv;
#pragma unroll
        for (int o = 16; o; o >>= 1) mx = fmaxf(mx, __shfl_xor_sync(0xffffffffu, mx, o));
        float e = __expf(wv - mx);
        float sm = e;
#pragma unroll
        for (int o = 16; o; o >>= 1) sm += __shfl_xor_sync(0xffffffffu, sm, o);
        sw[t] = e * __frcp_rn(sm);
        int elem = cids[t] - 1;
        const int start4 = 1 + 8192 + 4096 + 2048;
        sp0[t] = __ldg(&pids[elem * 2])     - start4;
        sp1[t] = __ldg(&pids[elem * 2 + 1]) - start4;
    }
    __syncthreads();
    cudaGridDependencySynchronize();              // wait for sum3's s3
    const uint2* s3 = (const uint2*)(g_bf + S3O);
    float a0 = 0.f, a1 = 0.f, a2 = 0.f, a3 = 0.f;
#pragma unroll
    for (int c = 0; c < 32; c++) {
        uint2 u0 = s3[(unsigned)sp0[c] * 256 + t];
        uint2 u1 = s3[(unsigned)sp1[c] * 256 + t];
        float wv = sw[c];
        a0 = fmaf(wv, (lo_bf(u0.x) * S3_SCALE) * (lo_bf(u1.x) * S3_SCALE), a0);
        a1 = fmaf(wv, (hi_bf(u0.x) * S3_SCALE) * (hi_bf(u1.x) * S3_SCALE), a1);
        a2 = fmaf(wv, (lo_bf(u0.y) * S3_SCALE) * (lo_bf(u1.y) * S3_SCALE), a2);
        a3 = fmaf(wv, (hi_bf(u0.y) * S3_SCALE) * (hi_bf(u1.y) * S3_SCALE), a3);
    }
    float4 o;
    o.x = logf(a0) - LOG_S3SQ;
    o.y = logf(a1) - LOG_S3SQ;
    o.z = logf(a2) - LOG_S3SQ;
    o.w = logf(a3) - LOG_S3SQ;
    ((float4*)out)[t] = o;
}

// Host-side PDL launch helper: every kernel allows programmatic overlap with
// its stream predecessor; in-kernel cudaGridDependencySynchronize() provides
// the actual ordering.
template <typename F, typename... Args>
static inline void launch_pdl(unsigned grid, unsigned block, F func, Args... args) {
    cudaLaunchConfig_t cfg = {};
    cfg.gridDim  = dim3(grid, 1, 1);
    cfg.blockDim = dim3(block, 1, 1);
    cfg.dynamicSmemBytes = 0;
    cfg.stream = 0;
    cudaLaunchAttribute attr[1];
    attr[0].id = cudaLaunchAttributeProgrammaticStreamSerialization;
    attr[0].val.programmaticStreamSerializationAllowed = 1;
    cfg.attrs = attr;
    cfg.numAttrs = 1;
    cudaLaunchKernelEx(&cfg, func, args...);
}

extern "C" void kernel_launch(void* const* d_in, const int* in_sizes, int n_in,
                              void* d_out, int out_size) {
    const int*   x      = (const int*)d_in[0];
    const float* logits = (const float*)d_in[1];
    const float* w1     = (const float*)d_in[2];
    const float* w2     = (const float*)d_in[3];
    const float* w3     = (const float*)d_in[4];
    const float* w4     = (const float*)d_in[5];
    const int*   pids1  = (const int*)d_in[6];
    const int*   pids2  = (const int*)d_in[7];
    const int*   pids3  = (const int*)d_in[8];
    const int*   pids4  = (const int*)d_in[9];
    const int*   cids1  = (const int*)d_in[10];
    const int*   cids2  = (const int*)d_in[11];
    const int*   cids3  = (const int*)d_in[12];
    const int*   cids4  = (const int*)d_in[13];

    // Input layer (reads only harness inputs; no PDL attr needed but harmless
    // to launch normally).
    k_inp<<<NV, 256>>>(logits, x);

    // Layer 1: prod -> fp8 em1, fp8 gather sum -> bf16 s1.
    launch_pdl(8192 / 4, 256, k_prod8, pids1);
    launch_pdl(4096, 128, k_sum8, cids1, w1);

    // Layer 2 (s1 ids start 8193).
    launch_pdl(4096 / 4, 256, k_prod, EMO, S1O, pids2, 1 + 8192);
    launch_pdl(2048, 128, k_sum, S2O, EMO, cids2, w2);

    // Layer 3 (s2 ids start 12289).
    launch_pdl(2048 / 4, 256, k_prod, EMO, S2O, pids3, 1 + 8192 + 4096);
    launch_pdl(1024, 128, k_sum, S3O, EMO, cids3, w3);

    // Layer 4 (prod+sum) fused into the root kernel, with 2^60 scaling.
    launch_pdl(1, 256, k_root, (float*)d_out, cids4, pids4, w4);
}